// round 1
// baseline (speedup 1.0000x reference)
#include <cuda_runtime.h>
#include <cuda_bf16.h>
#include <stddef.h>

// Problem constants
#define B_  8
#define N_  1024
#define DIM_ 768
#define H_  12
#define D_  64
#define SCALE_ 0.125f
#define EPS_ 1e-5f

// ---------------- scratch (static device globals; allocation-free) -------------
__device__ float g_q[(size_t)B_ * H_ * N_ * D_];        // 25 MB  [B,H,N,D]
__device__ float g_v[(size_t)B_ * H_ * N_ * D_];        // 25 MB  [B,H,N,D]
__device__ float g_attn[(size_t)B_ * H_ * N_ * N_];     // 402 MB [B,H,N,N] (scaled scores)
__device__ float g_obuf[(size_t)B_ * N_ * DIM_];        // 25 MB  [B,N,C]
__device__ float g_part[2][B_ * H_ * 64];               // per-block sum/sumsq partials
__device__ float g_g[H_];                               // per-head logits scale

__device__ __forceinline__ float warp_red(float v) {
#pragma unroll
    for (int o = 16; o; o >>= 1) v += __shfl_xor_sync(0xffffffffu, v, o);
    return v;
}

// ============================================================================
// K1: qv = x @ w_qv^T, scatter into q/v [B,H,N,D]
// C[m,e] = sum_c X[m,c] * W[e,c]; M=8192, E=1536, K=768
// grid (12, 64), 256 threads, 128x128 tile, 8x8 per thread
// ============================================================================
__global__ __launch_bounds__(256) void qv_gemm_kernel(
    const float* __restrict__ X, const float* __restrict__ W) {
    __shared__ float As[16][128];
    __shared__ float Bs[16][128];
    const int tid = threadIdx.x;
    const int ty = tid >> 4, tx = tid & 15;
    const int m0 = blockIdx.y * 128;
    const int e0 = blockIdx.x * 128;

    float acc[8][8];
#pragma unroll
    for (int i = 0; i < 8; i++)
#pragma unroll
        for (int j = 0; j < 8; j++) acc[i][j] = 0.0f;

    for (int k0 = 0; k0 < DIM_; k0 += 16) {
#pragma unroll
        for (int l = 0; l < 2; l++) {
            int f = tid + l * 256;              // [0,512)
            int r = f >> 2;                     // 0..127
            int c4 = (f & 3) * 4;               // 0..12
            float4 a = *(const float4*)&X[(size_t)(m0 + r) * DIM_ + k0 + c4];
            As[c4 + 0][r] = a.x; As[c4 + 1][r] = a.y; As[c4 + 2][r] = a.z; As[c4 + 3][r] = a.w;
            float4 b = *(const float4*)&W[(size_t)(e0 + r) * DIM_ + k0 + c4];
            Bs[c4 + 0][r] = b.x; Bs[c4 + 1][r] = b.y; Bs[c4 + 2][r] = b.z; Bs[c4 + 3][r] = b.w;
        }
        __syncthreads();
#pragma unroll
        for (int k = 0; k < 16; k++) {
            float a[8], b[8];
            *(float4*)&a[0] = *(const float4*)&As[k][ty * 4];
            *(float4*)&a[4] = *(const float4*)&As[k][64 + ty * 4];
            *(float4*)&b[0] = *(const float4*)&Bs[k][tx * 4];
            *(float4*)&b[4] = *(const float4*)&Bs[k][64 + tx * 4];
#pragma unroll
            for (int i = 0; i < 8; i++)
#pragma unroll
                for (int j = 0; j < 8; j++) acc[i][j] += a[i] * b[j];
        }
        __syncthreads();
    }

    // epilogue: scatter to q / v with [B,H,N,D] layout
#pragma unroll
    for (int ig = 0; ig < 2; ig++) {
#pragma unroll
        for (int ii = 0; ii < 4; ii++) {
            int i = ig * 4 + ii;
            int m = m0 + ig * 64 + ty * 4 + ii;
            int b = m >> 10, n = m & 1023;
#pragma unroll
            for (int jg = 0; jg < 2; jg++) {
                int e = e0 + jg * 64 + tx * 4;
                float4 val = make_float4(acc[i][jg * 4 + 0], acc[i][jg * 4 + 1],
                                         acc[i][jg * 4 + 2], acc[i][jg * 4 + 3]);
                if (e < DIM_) {
                    int h = e >> 6, d = e & 63;
                    *(float4*)&g_q[(((size_t)b * H_ + h) * N_ + n) * D_ + d] = val;
                } else {
                    int e2 = e - DIM_;
                    int h = e2 >> 6, d = e2 & 63;
                    *(float4*)&g_v[(((size_t)b * H_ + h) * N_ + n) * D_ + d] = val;
                }
            }
        }
    }
}

// ============================================================================
// K2: scores: S[b,h,n,m] = (q . k + bias) * SCALE; store to g_attn; emit
// deterministic per-block sum/sumsq partials.
// grid (8, 8, 96): x = m-tile, y = n-tile, z = b*H+h. 256 threads, 128x128 tile.
// ============================================================================
__global__ __launch_bounds__(256) void scores_kernel(
    const float* __restrict__ Kx, const float* __restrict__ Bias) {
    __shared__ float Qs[32][128];
    __shared__ float Ks[32][128];
    const int tid = threadIdx.x;
    const int ty = tid >> 4, tx = tid & 15;
    const int bh = blockIdx.z;
    const int h = bh % H_;
    const int n0 = blockIdx.y * 128;
    const int m0 = blockIdx.x * 128;

    const float* qptr = g_q + ((size_t)bh * N_ + n0) * D_;
    const float* kptr = Kx + ((size_t)h * N_ + m0) * D_;

    float acc[8][8];
#pragma unroll
    for (int i = 0; i < 8; i++)
#pragma unroll
        for (int j = 0; j < 8; j++) acc[i][j] = 0.0f;

#pragma unroll 1
    for (int k0 = 0; k0 < D_; k0 += 32) {
#pragma unroll
        for (int l = 0; l < 4; l++) {
            int f = tid + l * 256;          // [0,1024)
            int r = f >> 3;                 // 0..127
            int c4 = (f & 7) * 4;           // 0..28
            float4 a = *(const float4*)&qptr[(size_t)r * D_ + k0 + c4];
            Qs[c4 + 0][r] = a.x; Qs[c4 + 1][r] = a.y; Qs[c4 + 2][r] = a.z; Qs[c4 + 3][r] = a.w;
            float4 b = *(const float4*)&kptr[(size_t)r * D_ + k0 + c4];
            Ks[c4 + 0][r] = b.x; Ks[c4 + 1][r] = b.y; Ks[c4 + 2][r] = b.z; Ks[c4 + 3][r] = b.w;
        }
        __syncthreads();
#pragma unroll 8
        for (int k = 0; k < 32; k++) {
            float a[8], b[8];
            *(float4*)&a[0] = *(const float4*)&Qs[k][ty * 4];
            *(float4*)&a[4] = *(const float4*)&Qs[k][64 + ty * 4];
            *(float4*)&b[0] = *(const float4*)&Ks[k][tx * 4];
            *(float4*)&b[4] = *(const float4*)&Ks[k][64 + tx * 4];
#pragma unroll
            for (int i = 0; i < 8; i++)
#pragma unroll
                for (int j = 0; j < 8; j++) acc[i][j] += a[i] * b[j];
        }
        __syncthreads();
    }

    float s1 = 0.0f, s2 = 0.0f;
#pragma unroll
    for (int ig = 0; ig < 2; ig++) {
#pragma unroll
        for (int ii = 0; ii < 4; ii++) {
            int i = ig * 4 + ii;
            int n = n0 + ig * 64 + ty * 4 + ii;
            size_t brow = ((size_t)h * N_ + n) * N_;
            size_t arow = ((size_t)bh * N_ + n) * N_;
#pragma unroll
            for (int jg = 0; jg < 2; jg++) {
                int m = m0 + jg * 64 + tx * 4;
                float4 bb = *(const float4*)&Bias[brow + m];
                float4 o;
                o.x = (acc[i][jg * 4 + 0] + bb.x) * SCALE_;
                o.y = (acc[i][jg * 4 + 1] + bb.y) * SCALE_;
                o.z = (acc[i][jg * 4 + 2] + bb.z) * SCALE_;
                o.w = (acc[i][jg * 4 + 3] + bb.w) * SCALE_;
                *(float4*)&g_attn[arow + m] = o;
                s1 += o.x + o.y + o.z + o.w;
                s2 += o.x * o.x + o.y * o.y + o.z * o.z + o.w * o.w;
            }
        }
    }
    // deterministic block reduction -> partials
    s1 = warp_red(s1);
    s2 = warp_red(s2);
    __shared__ float rs[2][8];
    int wid = tid >> 5, lane = tid & 31;
    if (lane == 0) { rs[0][wid] = s1; rs[1][wid] = s2; }
    __syncthreads();
    if (tid == 0) {
        float a = 0.0f, b = 0.0f;
#pragma unroll
        for (int w = 0; w < 8; w++) { a += rs[0][w]; b += rs[1][w]; }
        int bl = blockIdx.z * 64 + blockIdx.y * 8 + blockIdx.x;
        g_part[0][bl] = a;
        g_part[1][bl] = b;
    }
}

// ============================================================================
// K3: finalize per-head scale g_h = gamma_h * rsqrt(var_h + eps)
// grid (12), 256 threads; deterministic reduction of 512 partials per head
// ============================================================================
__global__ __launch_bounds__(256) void finalize_kernel(const float* __restrict__ gamma) {
    const int h = blockIdx.x;
    const int t = threadIdx.x;
    float s1 = 0.0f, s2 = 0.0f;
#pragma unroll
    for (int e = t; e < 512; e += 256) {
        int b = e >> 6, tile = e & 63;
        int idx = (b * H_ + h) * 64 + tile;
        s1 += g_part[0][idx];
        s2 += g_part[1][idx];
    }
    s1 = warp_red(s1);
    s2 = warp_red(s2);
    __shared__ float r1[8], r2[8];
    int wid = t >> 5, lane = t & 31;
    if (lane == 0) { r1[wid] = s1; r2[wid] = s2; }
    __syncthreads();
    if (t == 0) {
        float S1 = 0.0f, S2 = 0.0f;
#pragma unroll
        for (int w = 0; w < 8; w++) { S1 += r1[w]; S2 += r2[w]; }
        const float cnt = (float)B_ * (float)N_ * (float)N_;
        float mean = S1 / cnt;
        float var = S2 / cnt - mean * mean;
        g_g[h] = gamma[h] * rsqrtf(var + EPS_);
    }
}

// ============================================================================
// K4: softmax (no-max, logits are tame) + P@V, output to [B,N,C] buffer.
// grid (16, 96): x = query row-block of 64, y = b*H+h. 256 threads (16x16).
// Each thread: 4 query rows x 4 d-cols of O.
// ============================================================================
__global__ __launch_bounds__(256) void softmax_pv_kernel() {
    __shared__ float P[64][68];
    __shared__ float Vs[64][68];
    const int tid = threadIdx.x;
    const int ty = tid >> 4, tx = tid & 15;
    const int bh = blockIdx.y;
    const int b = bh / H_, h = bh % H_;
    const int n0 = blockIdx.x * 64;

    const float gh = g_g[h];
    const float* arow = g_attn + ((size_t)bh * N_ + n0) * N_;
    const float* vptr = g_v + (size_t)bh * N_ * D_;

    float O[4][4];
#pragma unroll
    for (int i = 0; i < 4; i++)
#pragma unroll
        for (int j = 0; j < 4; j++) O[i][j] = 0.0f;
    float l[4] = {0.0f, 0.0f, 0.0f, 0.0f};

    for (int m0 = 0; m0 < N_; m0 += 64) {
        // exp phase: each thread handles rows ty*4..+3, cols tx*4..+3
#pragma unroll
        for (int i = 0; i < 4; i++) {
            int r = ty * 4 + i;
            float4 a = *(const float4*)&arow[(size_t)r * N_ + m0 + tx * 4];
            float4 e;
            e.x = __expf(a.x * gh);
            e.y = __expf(a.y * gh);
            e.z = __expf(a.z * gh);
            e.w = __expf(a.w * gh);
            *(float4*)&P[r][tx * 4] = e;
            l[i] += e.x + e.y + e.z + e.w;
        }
        // V tile load [64 x 64]
#pragma unroll
        for (int l2 = 0; l2 < 4; l2++) {
            int f = tid + l2 * 256;     // [0,1024)
            int r = f >> 4, c4 = (f & 15) * 4;
            *(float4*)&Vs[r][c4] = *(const float4*)&vptr[(size_t)(m0 + r) * D_ + c4];
        }
        __syncthreads();
        // PV
#pragma unroll 8
        for (int m = 0; m < 64; m++) {
            float4 vv = *(const float4*)&Vs[m][tx * 4];
#pragma unroll
            for (int i = 0; i < 4; i++) {
                float p = P[ty * 4 + i][m];
                O[i][0] += p * vv.x;
                O[i][1] += p * vv.y;
                O[i][2] += p * vv.z;
                O[i][3] += p * vv.w;
            }
        }
        __syncthreads();
    }

    // reduce row sums across the 16 tx lanes (within each 16-lane half-warp)
#pragma unroll
    for (int i = 0; i < 4; i++) {
        float s = l[i];
#pragma unroll
        for (int o = 8; o; o >>= 1) s += __shfl_xor_sync(0xffffffffu, s, o);
        l[i] = s;
    }

#pragma unroll
    for (int i = 0; i < 4; i++) {
        float inv = 1.0f / l[i];
        int n = n0 + ty * 4 + i;
        float4 o4 = make_float4(O[i][0] * inv, O[i][1] * inv, O[i][2] * inv, O[i][3] * inv);
        *(float4*)&g_obuf[((size_t)b * N_ + n) * DIM_ + h * D_ + tx * 4] = o4;
    }
}

// ============================================================================
// K5: out = obuf @ w_proj^T + b_proj.  M=8192, O=768, K=768.
// grid (6, 64), 256 threads, 128x128 tile.
// ============================================================================
__global__ __launch_bounds__(256) void proj_kernel(
    const float* __restrict__ Wp, const float* __restrict__ bp,
    float* __restrict__ Out) {
    __shared__ float As[16][128];
    __shared__ float Bs[16][128];
    const int tid = threadIdx.x;
    const int ty = tid >> 4, tx = tid & 15;
    const int m0 = blockIdx.y * 128;
    const int e0 = blockIdx.x * 128;

    float acc[8][8];
#pragma unroll
    for (int i = 0; i < 8; i++)
#pragma unroll
        for (int j = 0; j < 8; j++) acc[i][j] = 0.0f;

    for (int k0 = 0; k0 < DIM_; k0 += 16) {
#pragma unroll
        for (int l = 0; l < 2; l++) {
            int f = tid + l * 256;
            int r = f >> 2;
            int c4 = (f & 3) * 4;
            float4 a = *(const float4*)&g_obuf[(size_t)(m0 + r) * DIM_ + k0 + c4];
            As[c4 + 0][r] = a.x; As[c4 + 1][r] = a.y; As[c4 + 2][r] = a.z; As[c4 + 3][r] = a.w;
            float4 b = *(const float4*)&Wp[(size_t)(e0 + r) * DIM_ + k0 + c4];
            Bs[c4 + 0][r] = b.x; Bs[c4 + 1][r] = b.y; Bs[c4 + 2][r] = b.z; Bs[c4 + 3][r] = b.w;
        }
        __syncthreads();
#pragma unroll
        for (int k = 0; k < 16; k++) {
            float a[8], b[8];
            *(float4*)&a[0] = *(const float4*)&As[k][ty * 4];
            *(float4*)&a[4] = *(const float4*)&As[k][64 + ty * 4];
            *(float4*)&b[0] = *(const float4*)&Bs[k][tx * 4];
            *(float4*)&b[4] = *(const float4*)&Bs[k][64 + tx * 4];
#pragma unroll
            for (int i = 0; i < 8; i++)
#pragma unroll
                for (int j = 0; j < 8; j++) acc[i][j] += a[i] * b[j];
        }
        __syncthreads();
    }

#pragma unroll
    for (int ig = 0; ig < 2; ig++) {
#pragma unroll
        for (int ii = 0; ii < 4; ii++) {
            int i = ig * 4 + ii;
            int m = m0 + ig * 64 + ty * 4 + ii;
#pragma unroll
            for (int jg = 0; jg < 2; jg++) {
                int e = e0 + jg * 64 + tx * 4;
                float4 bb = *(const float4*)&bp[e];
                float4 val = make_float4(acc[i][jg * 4 + 0] + bb.x,
                                         acc[i][jg * 4 + 1] + bb.y,
                                         acc[i][jg * 4 + 2] + bb.z,
                                         acc[i][jg * 4 + 3] + bb.w);
                *(float4*)&Out[(size_t)m * DIM_ + e] = val;
            }
        }
    }
}

// ============================================================================
// launch
// ============================================================================
extern "C" void kernel_launch(void* const* d_in, const int* in_sizes, int n_in,
                              void* d_out, int out_size) {
    const float* x       = (const float*)d_in[0];
    const float* w_qv    = (const float*)d_in[1];
    const float* ext_k   = (const float*)d_in[2];
    const float* ext_bias= (const float*)d_in[3];
    const float* bn_gamma= (const float*)d_in[4];
    // d_in[5] = bn_beta: cancels inside softmax (constant along key axis)
    const float* w_proj  = (const float*)d_in[6];
    const float* b_proj  = (const float*)d_in[7];
    float* out = (float*)d_out;

    qv_gemm_kernel<<<dim3(12, 64), 256>>>(x, w_qv);
    scores_kernel<<<dim3(8, 8, B_ * H_), 256>>>(ext_k, ext_bias);
    finalize_kernel<<<dim3(H_), 256>>>(bn_gamma);
    softmax_pv_kernel<<<dim3(16, B_ * H_), 256>>>();
    proj_kernel<<<dim3(6, 64), 256>>>(w_proj, b_proj, out);
}

// round 4
// speedup vs baseline: 1.4789x; 1.4789x over previous
#include <cuda_runtime.h>
#include <stdint.h>
#include <stddef.h>

#define B_   8
#define N_   1024
#define DIM_ 768
#define H_   12
#define D_   64
#define SCALE_ 0.125f
#define EPS_ 1e-5f

// ---------------- scratch ----------------
__device__ float g_q[(size_t)B_ * H_ * N_ * D_];    // [B,H,N,D]
__device__ float g_vT[(size_t)B_ * H_ * D_ * N_];   // [B,H,D,N] (transposed V)
__device__ float g_obuf[(size_t)B_ * N_ * DIM_];    // [B,N,C]
__device__ float g_part[2][96 * 16];                // per-block sum/sumsq partials
__device__ float g_g[H_];                           // per-head logits scale

__device__ __forceinline__ float warp_red(float v) {
#pragma unroll
    for (int o = 16; o; o >>= 1) v += __shfl_xor_sync(0xffffffffu, v, o);
    return v;
}

__device__ __forceinline__ uint32_t f2tf(float f) {
    uint32_t u;
    asm("cvt.rna.tf32.f32 %0, %1;" : "=r"(u) : "f"(f));
    return u;
}

// D += A(16x8) * B(8x8), tf32
__device__ __forceinline__ void mma_tf32(float4& d, uint32_t a0, uint32_t a1,
                                         uint32_t a2, uint32_t a3,
                                         uint32_t b0, uint32_t b1) {
    asm volatile(
        "mma.sync.aligned.m16n8k8.row.col.f32.tf32.tf32.f32 "
        "{%0,%1,%2,%3},{%4,%5,%6,%7},{%8,%9},{%0,%1,%2,%3};"
        : "+f"(d.x), "+f"(d.y), "+f"(d.z), "+f"(d.w)
        : "r"(a0), "r"(a1), "r"(a2), "r"(a3), "r"(b0), "r"(b1));
}

// k-permutation within an 8-block: original col c -> 2*(c&3) | (c>>2)
// makes frag pairs (k, k+4) adjacent so they load as one LDS.64
__device__ __forceinline__ int perm8(int c) { return ((c & 3) << 1) | ((c >> 2) & 1); }

// ============================================================================
// K1: qv GEMM (tf32): C[m,e] = sum_c X[m,c] W[e,c]; M=8192, E=1536, K=768
// block 128x128, 8 warps (4m x 2n), warp tile 32x64
// ============================================================================
__global__ __launch_bounds__(256) void qv_gemm(const float* __restrict__ X,
                                               const float* __restrict__ W) {
    __shared__ uint32_t As[128][36];
    __shared__ uint32_t Bs[128][36];
    const int tid = threadIdx.x, lane = tid & 31, w = tid >> 5;
    const int g = lane >> 2, t = lane & 3;
    const int wm = (w & 3) * 32, wn = (w >> 2) * 64;
    const int m0 = blockIdx.y * 128, e0 = blockIdx.x * 128;

    float4 acc[2][8];
#pragma unroll
    for (int i = 0; i < 2; i++)
#pragma unroll
        for (int j = 0; j < 8; j++) acc[i][j] = make_float4(0.f, 0.f, 0.f, 0.f);

    for (int kc = 0; kc < DIM_; kc += 32) {
#pragma unroll
        for (int i = 0; i < 4; i++) {
            int f = tid + i * 256;          // [0,1024)
            int r = f >> 3;
            int c4 = (f & 7) * 4;           // 0..28
            int bc = c4 & ~7;
            int p2 = (c4 >> 2) & 1;
            float4 a = *(const float4*)&X[(size_t)(m0 + r) * DIM_ + kc + c4];
            As[r][bc + p2 + 0] = f2tf(a.x);
            As[r][bc + p2 + 2] = f2tf(a.y);
            As[r][bc + p2 + 4] = f2tf(a.z);
            As[r][bc + p2 + 6] = f2tf(a.w);
            float4 b = *(const float4*)&W[(size_t)(e0 + r) * DIM_ + kc + c4];
            Bs[r][bc + p2 + 0] = f2tf(b.x);
            Bs[r][bc + p2 + 2] = f2tf(b.y);
            Bs[r][bc + p2 + 4] = f2tf(b.z);
            Bs[r][bc + p2 + 6] = f2tf(b.w);
        }
        __syncthreads();
#pragma unroll
        for (int ks = 0; ks < 4; ks++) {
            int kb = ks * 8;
            uint2 A0[2], A1[2];
#pragma unroll
            for (int mf = 0; mf < 2; mf++) {
                A0[mf] = *(const uint2*)&As[wm + mf * 16 + g][kb + 2 * t];
                A1[mf] = *(const uint2*)&As[wm + mf * 16 + 8 + g][kb + 2 * t];
            }
            uint2 Bv[8];
#pragma unroll
            for (int nf = 0; nf < 8; nf++)
                Bv[nf] = *(const uint2*)&Bs[wn + nf * 8 + g][kb + 2 * t];
#pragma unroll
            for (int mf = 0; mf < 2; mf++)
#pragma unroll
                for (int nf = 0; nf < 8; nf++)
                    mma_tf32(acc[mf][nf], A0[mf].x, A1[mf].x, A0[mf].y, A1[mf].y,
                             Bv[nf].x, Bv[nf].y);
        }
        __syncthreads();
    }

#pragma unroll
    for (int mf = 0; mf < 2; mf++) {
#pragma unroll
        for (int nf = 0; nf < 8; nf++) {
            int row = m0 + wm + mf * 16 + g;
            int col = e0 + wn + nf * 8 + 2 * t;
            int b = row >> 10, n = row & 1023;
            float4 c = acc[mf][nf];
            if (col < DIM_) {
                int h = col >> 6, d = col & 63;
                size_t base = (((size_t)b * H_ + h) * N_ + n) * D_ + d;
                *(float2*)&g_q[base] = make_float2(c.x, c.y);
                *(float2*)&g_q[base + 8 * D_] = make_float2(c.z, c.w);
            } else {
                int e2 = col - DIM_;
                int h = e2 >> 6, d = e2 & 63;
                size_t base = (((size_t)b * H_ + h) * D_ + d) * N_ + n;
                g_vT[base] = c.x;
                g_vT[base + N_] = c.y;
                g_vT[base + 8] = c.z;
                g_vT[base + N_ + 8] = c.w;
            }
        }
    }
}

// ============================================================================
// K2: stats — recompute scores tf32, accumulate sum & sumsq (no store)
// grid (16 n-tiles, 96 bh); 8 warps (4n x 2m), warp tile 16x32; m-tile 64
// ============================================================================
__global__ __launch_bounds__(256) void stats_kernel(const float* __restrict__ Kx,
                                                    const float* __restrict__ Bias) {
    __shared__ uint32_t Qs[64][68];
    __shared__ uint32_t Ks[64][68];
    const int tid = threadIdx.x, lane = tid & 31, w = tid >> 5;
    const int g = lane >> 2, t = lane & 3;
    const int wn = (w >> 1) * 16, wm = (w & 1) * 32;
    const int bh = blockIdx.y, h = bh % H_;
    const int n0 = blockIdx.x * 64;

    const float* qp = g_q + ((size_t)bh * N_ + n0) * D_;
#pragma unroll
    for (int i = 0; i < 4; i++) {
        int f = tid + i * 256;
        int r = f >> 4;
        int c4 = (f & 15) * 4;
        int bc = c4 & ~7, p2 = (c4 >> 2) & 1;
        float4 a = *(const float4*)&qp[(size_t)r * D_ + c4];
        Qs[r][bc + p2 + 0] = f2tf(a.x);
        Qs[r][bc + p2 + 2] = f2tf(a.y);
        Qs[r][bc + p2 + 4] = f2tf(a.z);
        Qs[r][bc + p2 + 6] = f2tf(a.w);
    }

    float s1 = 0.f, s2 = 0.f;
    for (int m0 = 0; m0 < N_; m0 += 64) {
        __syncthreads();
        const float* kp = Kx + ((size_t)h * N_ + m0) * D_;
#pragma unroll
        for (int i = 0; i < 4; i++) {
            int f = tid + i * 256;
            int r = f >> 4;
            int c4 = (f & 15) * 4;
            int bc = c4 & ~7, p2 = (c4 >> 2) & 1;
            float4 a = *(const float4*)&kp[(size_t)r * D_ + c4];
            Ks[r][bc + p2 + 0] = f2tf(a.x);
            Ks[r][bc + p2 + 2] = f2tf(a.y);
            Ks[r][bc + p2 + 4] = f2tf(a.z);
            Ks[r][bc + p2 + 6] = f2tf(a.w);
        }
        __syncthreads();

        float4 acc[4];
#pragma unroll
        for (int j = 0; j < 4; j++) acc[j] = make_float4(0.f, 0.f, 0.f, 0.f);

#pragma unroll
        for (int kb = 0; kb < 64; kb += 8) {
            uint2 A0 = *(const uint2*)&Qs[wn + g][kb + 2 * t];
            uint2 A1 = *(const uint2*)&Qs[wn + 8 + g][kb + 2 * t];
#pragma unroll
            for (int nf = 0; nf < 4; nf++) {
                uint2 Bv = *(const uint2*)&Ks[wm + nf * 8 + g][kb + 2 * t];
                mma_tf32(acc[nf], A0.x, A1.x, A0.y, A1.y, Bv.x, Bv.y);
            }
        }

#pragma unroll
        for (int nf = 0; nf < 4; nf++) {
            int rr = n0 + wn + g;
            int cc = m0 + wm + nf * 8 + 2 * t;
            const float* bp = Bias + ((size_t)h * N_ + rr) * N_ + cc;
            float2 b0 = *(const float2*)bp;
            float2 b1 = *(const float2*)(bp + 8 * N_);
            float4 a = acc[nf];
            float v0 = (a.x + b0.x) * SCALE_;
            float v1 = (a.y + b0.y) * SCALE_;
            float v2 = (a.z + b1.x) * SCALE_;
            float v3 = (a.w + b1.y) * SCALE_;
            s1 += v0 + v1 + v2 + v3;
            s2 += v0 * v0 + v1 * v1 + v2 * v2 + v3 * v3;
        }
    }

    s1 = warp_red(s1);
    s2 = warp_red(s2);
    __shared__ float rs[2][8];
    if (lane == 0) { rs[0][w] = s1; rs[1][w] = s2; }
    __syncthreads();
    if (tid == 0) {
        float a = 0.f, b = 0.f;
#pragma unroll
        for (int i = 0; i < 8; i++) { a += rs[0][i]; b += rs[1][i]; }
        int bl = blockIdx.y * 16 + blockIdx.x;
        g_part[0][bl] = a;
        g_part[1][bl] = b;
    }
}

// ============================================================================
// K3: finalize g_h = gamma_h * rsqrt(var_h + eps). grid (12), 128 threads.
// ============================================================================
__global__ __launch_bounds__(128) void finalize_kernel(const float* __restrict__ gamma) {
    const int h = blockIdx.x, tid = threadIdx.x;
    int bb = tid >> 4, tt = tid & 15;
    int idx = (bb * H_ + h) * 16 + tt;
    float s1 = g_part[0][idx];
    float s2 = g_part[1][idx];
    s1 = warp_red(s1);
    s2 = warp_red(s2);
    __shared__ float r1[4], r2[4];
    if ((tid & 31) == 0) { r1[tid >> 5] = s1; r2[tid >> 5] = s2; }
    __syncthreads();
    if (tid == 0) {
        float S1 = r1[0] + r1[1] + r1[2] + r1[3];
        float S2 = r2[0] + r2[1] + r2[2] + r2[3];
        const float cnt = (float)B_ * (float)N_ * (float)N_;
        float mean = S1 / cnt;
        float var = S2 / cnt - mean * mean;
        g_g[h] = gamma[h] * rsqrtf(var + EPS_);
    }
}

// ============================================================================
// K4: fused scores->exp->PV (flash style, tf32 mma both GEMMs)
// grid (16 n-tiles, 96 bh); 8 warps; q-tile 64, key-tile 32
// S warp tile: 16n x 16m (4 n-groups x 2 m-halves)
// PV warp tile: 16n x 32d (same 4 n-groups x 2 d-halves)
// smem: Qs 17408 + Ks 8704 + Vs 9216 + Ps 9216 + ls 512 = 45056 B (static)
// ============================================================================
__global__ __launch_bounds__(256) void fused_attn(const float* __restrict__ Kx,
                                                  const float* __restrict__ Bias) {
    __shared__ uint32_t Qs[64][68];
    __shared__ uint32_t Ks[32][68];   // K tile: rows m_local(32), cols d(64) perm
    __shared__ uint32_t Vs[64][36];   // V^T tile: rows d(64), cols m_local(32) perm
    __shared__ uint32_t Ps[64][36];   // P tile: rows n(64), cols m_local(32) perm
    __shared__ float ls[2][64];

    const int tid = threadIdx.x, lane = tid & 31, w = tid >> 5;
    const int g = lane >> 2, t = lane & 3;
    const int wn = (w >> 1) * 16;     // 4 n-groups of 16 rows
    const int half = w & 1;
    const int wmS = half * 16;        // S: m-half within 32-tile
    const int wd = half * 32;         // PV: d-half
    const int bh = blockIdx.y, b = bh / H_, h = bh % H_;
    const int n0 = blockIdx.x * 64;
    const float sg = SCALE_ * g_g[h];
    const int pc0 = perm8(2 * t), pc1 = perm8(2 * t + 1);

    const float* qp = g_q + ((size_t)bh * N_ + n0) * D_;
#pragma unroll
    for (int i = 0; i < 4; i++) {
        int f = tid + i * 256;
        int r = f >> 4;
        int c4 = (f & 15) * 4;
        int bc = c4 & ~7, p2 = (c4 >> 2) & 1;
        float4 a = *(const float4*)&qp[(size_t)r * D_ + c4];
        Qs[r][bc + p2 + 0] = f2tf(a.x);
        Qs[r][bc + p2 + 2] = f2tf(a.y);
        Qs[r][bc + p2 + 4] = f2tf(a.z);
        Qs[r][bc + p2 + 6] = f2tf(a.w);
    }

    float4 O[4];
#pragma unroll
    for (int j = 0; j < 4; j++) O[j] = make_float4(0.f, 0.f, 0.f, 0.f);
    float l0 = 0.f, l1 = 0.f;

    for (int m0 = 0; m0 < N_; m0 += 32) {
        __syncthreads();   // previous PV done; Ks/Vs/Ps reusable
        // K tile: 32 rows x 64 d
        const float* kp = Kx + ((size_t)h * N_ + m0) * D_;
#pragma unroll
        for (int i = 0; i < 2; i++) {
            int f = tid + i * 256;          // [0,512)
            int r = f >> 4;                 // 0..31
            int c4 = (f & 15) * 4;
            int bc = c4 & ~7, p2 = (c4 >> 2) & 1;
            float4 a = *(const float4*)&kp[(size_t)r * D_ + c4];
            Ks[r][bc + p2 + 0] = f2tf(a.x);
            Ks[r][bc + p2 + 2] = f2tf(a.y);
            Ks[r][bc + p2 + 4] = f2tf(a.z);
            Ks[r][bc + p2 + 6] = f2tf(a.w);
        }
        // V^T tile: 64 d rows x 32 m cols
        const float* vp = g_vT + (size_t)bh * D_ * N_ + m0;
#pragma unroll
        for (int i = 0; i < 2; i++) {
            int f = tid + i * 256;          // [0,512)
            int r = f >> 3;                 // 0..63 (d)
            int c4 = (f & 7) * 4;           // 0..28 (m)
            int bc = c4 & ~7, p2 = (c4 >> 2) & 1;
            float4 v = *(const float4*)&vp[(size_t)r * N_ + c4];
            Vs[r][bc + p2 + 0] = f2tf(v.x);
            Vs[r][bc + p2 + 2] = f2tf(v.y);
            Vs[r][bc + p2 + 4] = f2tf(v.z);
            Vs[r][bc + p2 + 6] = f2tf(v.w);
        }
        __syncthreads();

        // S = Q @ K^T : warp computes 16n x 16m (nf 0..1)
        float4 S[2];
        S[0] = make_float4(0.f, 0.f, 0.f, 0.f);
        S[1] = make_float4(0.f, 0.f, 0.f, 0.f);
#pragma unroll
        for (int kb = 0; kb < 64; kb += 8) {
            uint2 A0 = *(const uint2*)&Qs[wn + g][kb + 2 * t];
            uint2 A1 = *(const uint2*)&Qs[wn + 8 + g][kb + 2 * t];
#pragma unroll
            for (int nf = 0; nf < 2; nf++) {
                uint2 Bv = *(const uint2*)&Ks[wmS + nf * 8 + g][kb + 2 * t];
                mma_tf32(S[nf], A0.x, A1.x, A0.y, A1.y, Bv.x, Bv.y);
            }
        }

        // epilogue: bias, exp, row-sum, write P (tf32, k-permuted along m)
#pragma unroll
        for (int nf = 0; nf < 2; nf++) {
            int rr = n0 + wn + g;
            int cc = m0 + wmS + nf * 8 + 2 * t;
            const float* bp = Bias + ((size_t)h * N_ + rr) * N_ + cc;
            float2 b0 = *(const float2*)bp;
            float2 b1 = *(const float2*)(bp + 8 * N_);
            float p0 = __expf((S[nf].x + b0.x) * sg);
            float p1 = __expf((S[nf].y + b0.y) * sg);
            float p2v = __expf((S[nf].z + b1.x) * sg);
            float p3 = __expf((S[nf].w + b1.y) * sg);
            l0 += p0 + p1;
            l1 += p2v + p3;
            int base = wmS + nf * 8;
            Ps[wn + g][base + pc0] = f2tf(p0);
            Ps[wn + g][base + pc1] = f2tf(p1);
            Ps[wn + 8 + g][base + pc0] = f2tf(p2v);
            Ps[wn + 8 + g][base + pc1] = f2tf(p3);
        }
        __syncthreads();

        // O += P @ V : warp covers rows [wn,wn+16), d cols [wd, wd+32)
#pragma unroll
        for (int kb = 0; kb < 32; kb += 8) {
            uint2 A0 = *(const uint2*)&Ps[wn + g][kb + 2 * t];
            uint2 A1 = *(const uint2*)&Ps[wn + 8 + g][kb + 2 * t];
#pragma unroll
            for (int df = 0; df < 4; df++) {
                uint2 Bv = *(const uint2*)&Vs[wd + df * 8 + g][kb + 2 * t];
                mma_tf32(O[df], A0.x, A1.x, A0.y, A1.y, Bv.x, Bv.y);
            }
        }
    }

    __syncthreads();
    // row sums: reduce over 4 lanes of each quad, then over the 2 m-halves
    l0 += __shfl_xor_sync(0xffffffffu, l0, 1);
    l0 += __shfl_xor_sync(0xffffffffu, l0, 2);
    l1 += __shfl_xor_sync(0xffffffffu, l1, 1);
    l1 += __shfl_xor_sync(0xffffffffu, l1, 2);
    if (t == 0) {
        ls[half][wn + g] = l0;
        ls[half][wn + 8 + g] = l1;
    }
    __syncthreads();

#pragma unroll
    for (int df = 0; df < 4; df++) {
        int rr = wn + g;
        int d = wd + df * 8 + 2 * t;
        float inv0 = 1.0f / (ls[0][rr] + ls[1][rr]);
        float inv1 = 1.0f / (ls[0][rr + 8] + ls[1][rr + 8]);
        size_t o = ((size_t)b * N_ + n0 + rr) * DIM_ + h * D_ + d;
        *(float2*)&g_obuf[o] = make_float2(O[df].x * inv0, O[df].y * inv0);
        *(float2*)&g_obuf[o + 8 * DIM_] = make_float2(O[df].z * inv1, O[df].w * inv1);
    }
}

// ============================================================================
// K5: proj (tf32): out[m,e] = sum_c obuf[m,c] Wp[e,c] + bp[e]; E=768
// ============================================================================
__global__ __launch_bounds__(256) void proj_gemm(const float* __restrict__ Wp,
                                                 const float* __restrict__ bp,
                                                 float* __restrict__ Out) {
    __shared__ uint32_t As[128][36];
    __shared__ uint32_t Bs[128][36];
    const int tid = threadIdx.x, lane = tid & 31, w = tid >> 5;
    const int g = lane >> 2, t = lane & 3;
    const int wm = (w & 3) * 32, wn = (w >> 2) * 64;
    const int m0 = blockIdx.y * 128, e0 = blockIdx.x * 128;

    float4 acc[2][8];
#pragma unroll
    for (int i = 0; i < 2; i++)
#pragma unroll
        for (int j = 0; j < 8; j++) acc[i][j] = make_float4(0.f, 0.f, 0.f, 0.f);

    for (int kc = 0; kc < DIM_; kc += 32) {
#pragma unroll
        for (int i = 0; i < 4; i++) {
            int f = tid + i * 256;
            int r = f >> 3;
            int c4 = (f & 7) * 4;
            int bc = c4 & ~7, p2 = (c4 >> 2) & 1;
            float4 a = *(const float4*)&g_obuf[(size_t)(m0 + r) * DIM_ + kc + c4];
            As[r][bc + p2 + 0] = f2tf(a.x);
            As[r][bc + p2 + 2] = f2tf(a.y);
            As[r][bc + p2 + 4] = f2tf(a.z);
            As[r][bc + p2 + 6] = f2tf(a.w);
            float4 bv = *(const float4*)&Wp[(size_t)(e0 + r) * DIM_ + kc + c4];
            Bs[r][bc + p2 + 0] = f2tf(bv.x);
            Bs[r][bc + p2 + 2] = f2tf(bv.y);
            Bs[r][bc + p2 + 4] = f2tf(bv.z);
            Bs[r][bc + p2 + 6] = f2tf(bv.w);
        }
        __syncthreads();
#pragma unroll
        for (int ks = 0; ks < 4; ks++) {
            int kb = ks * 8;
            uint2 A0[2], A1[2];
#pragma unroll
            for (int mf = 0; mf < 2; mf++) {
                A0[mf] = *(const uint2*)&As[wm + mf * 16 + g][kb + 2 * t];
                A1[mf] = *(const uint2*)&As[wm + mf * 16 + 8 + g][kb + 2 * t];
            }
            uint2 Bv[8];
#pragma unroll
            for (int nf = 0; nf < 8; nf++)
                Bv[nf] = *(const uint2*)&Bs[wn + nf * 8 + g][kb + 2 * t];
#pragma unroll
            for (int mf = 0; mf < 2; mf++)
#pragma unroll
                for (int nf = 0; nf < 8; nf++)
                    mma_tf32(acc[mf][nf], A0[mf].x, A1[mf].x, A0[mf].y, A1[mf].y,
                             Bv[nf].x, Bv[nf].y);
        }
        __syncthreads();
    }

#pragma unroll
    for (int mf = 0; mf < 2; mf++) {
#pragma unroll
        for (int nf = 0; nf < 8; nf++) {
            int row = m0 + wm + mf * 16 + g;
            int col = e0 + wn + nf * 8 + 2 * t;
            float2 bb = *(const float2*)&bp[col];
            float4 c = acc[mf][nf];
            *(float2*)&Out[(size_t)row * DIM_ + col] =
                make_float2(c.x + bb.x, c.y + bb.y);
            *(float2*)&Out[(size_t)(row + 8) * DIM_ + col] =
                make_float2(c.z + bb.x, c.w + bb.y);
        }
    }
}

// ============================================================================
// launch
// ============================================================================
extern "C" void kernel_launch(void* const* d_in, const int* in_sizes, int n_in,
                              void* d_out, int out_size) {
    const float* x        = (const float*)d_in[0];
    const float* w_qv     = (const float*)d_in[1];
    const float* ext_k    = (const float*)d_in[2];
    const float* ext_bias = (const float*)d_in[3];
    const float* bn_gamma = (const float*)d_in[4];
    // d_in[5] = bn_beta: cancels inside softmax (constant along key axis)
    const float* w_proj   = (const float*)d_in[6];
    const float* b_proj   = (const float*)d_in[7];
    float* out = (float*)d_out;

    qv_gemm<<<dim3(12, 64), 256>>>(x, w_qv);
    stats_kernel<<<dim3(16, 96), 256>>>(ext_k, ext_bias);
    finalize_kernel<<<dim3(H_), 128>>>(bn_gamma);
    fused_attn<<<dim3(16, 96), 256>>>(ext_k, ext_bias);
    proj_gemm<<<dim3(6, 64), 256>>>(w_proj, b_proj, out);
}

// round 7
// speedup vs baseline: 1.6237x; 1.0979x over previous
#include <cuda_runtime.h>
#include <stdint.h>
#include <stddef.h>

#define B_   8
#define N_   1024
#define DIM_ 768
#define H_   12
#define D_   64
#define SCALE_ 0.125f
#define EPS_ 1e-5f

// ---------------- scratch ----------------
__device__ float g_q[(size_t)B_ * H_ * N_ * D_];    // [B,H,N,D]
__device__ float g_vT[(size_t)B_ * H_ * D_ * N_];   // [B,H,D,N] (transposed V)
__device__ float g_obuf[(size_t)B_ * N_ * DIM_];    // [B,N,C]
__device__ float g_part[2][96 * 8];                 // per-block sum/sumsq partials
__device__ float g_g[H_];                           // per-head logits scale

__device__ __forceinline__ float warp_red(float v) {
#pragma unroll
    for (int o = 16; o; o >>= 1) v += __shfl_xor_sync(0xffffffffu, v, o);
    return v;
}

__device__ __forceinline__ uint32_t f2tf(float f) {
    uint32_t u;
    asm("cvt.rna.tf32.f32 %0, %1;" : "=r"(u) : "f"(f));
    return u;
}

// D += A(16x8) * B(8x8), tf32
__device__ __forceinline__ void mma_tf32(float4& d, uint32_t a0, uint32_t a1,
                                         uint32_t a2, uint32_t a3,
                                         uint32_t b0, uint32_t b1) {
    asm volatile(
        "mma.sync.aligned.m16n8k8.row.col.f32.tf32.tf32.f32 "
        "{%0,%1,%2,%3},{%4,%5,%6,%7},{%8,%9},{%0,%1,%2,%3};"
        : "+f"(d.x), "+f"(d.y), "+f"(d.z), "+f"(d.w)
        : "r"(a0), "r"(a1), "r"(a2), "r"(a3), "r"(b0), "r"(b1));
}

// k-permutation within an 8-block: original col c -> 2*(c&3) | (c>>2)
__device__ __forceinline__ int perm8(int c) { return ((c & 3) << 1) | ((c >> 2) & 1); }

// ============================================================================
// K1: qv GEMM (tf32): C[m,e] = sum_c X[m,c] W[e,c]; M=8192, E=1536, K=768
// ============================================================================
__global__ __launch_bounds__(256) void qv_gemm(const float* __restrict__ X,
                                               const float* __restrict__ W) {
    __shared__ uint32_t As[128][36];
    __shared__ uint32_t Bs[128][36];
    const int tid = threadIdx.x, lane = tid & 31, w = tid >> 5;
    const int g = lane >> 2, t = lane & 3;
    const int wm = (w & 3) * 32, wn = (w >> 2) * 64;
    const int m0 = blockIdx.y * 128, e0 = blockIdx.x * 128;

    float4 acc[2][8];
#pragma unroll
    for (int i = 0; i < 2; i++)
#pragma unroll
        for (int j = 0; j < 8; j++) acc[i][j] = make_float4(0.f, 0.f, 0.f, 0.f);

    for (int kc = 0; kc < DIM_; kc += 32) {
#pragma unroll
        for (int i = 0; i < 4; i++) {
            int f = tid + i * 256;
            int r = f >> 3;
            int c4 = (f & 7) * 4;
            int bc = c4 & ~7;
            int p2 = (c4 >> 2) & 1;
            float4 a = *(const float4*)&X[(size_t)(m0 + r) * DIM_ + kc + c4];
            As[r][bc + p2 + 0] = f2tf(a.x);
            As[r][bc + p2 + 2] = f2tf(a.y);
            As[r][bc + p2 + 4] = f2tf(a.z);
            As[r][bc + p2 + 6] = f2tf(a.w);
            float4 b = *(const float4*)&W[(size_t)(e0 + r) * DIM_ + kc + c4];
            Bs[r][bc + p2 + 0] = f2tf(b.x);
            Bs[r][bc + p2 + 2] = f2tf(b.y);
            Bs[r][bc + p2 + 4] = f2tf(b.z);
            Bs[r][bc + p2 + 6] = f2tf(b.w);
        }
        __syncthreads();
#pragma unroll
        for (int ks = 0; ks < 4; ks++) {
            int kb = ks * 8;
            uint2 A0[2], A1[2];
#pragma unroll
            for (int mf = 0; mf < 2; mf++) {
                A0[mf] = *(const uint2*)&As[wm + mf * 16 + g][kb + 2 * t];
                A1[mf] = *(const uint2*)&As[wm + mf * 16 + 8 + g][kb + 2 * t];
            }
            uint2 Bv[8];
#pragma unroll
            for (int nf = 0; nf < 8; nf++)
                Bv[nf] = *(const uint2*)&Bs[wn + nf * 8 + g][kb + 2 * t];
#pragma unroll
            for (int mf = 0; mf < 2; mf++)
#pragma unroll
                for (int nf = 0; nf < 8; nf++)
                    mma_tf32(acc[mf][nf], A0[mf].x, A1[mf].x, A0[mf].y, A1[mf].y,
                             Bv[nf].x, Bv[nf].y);
        }
        __syncthreads();
    }

#pragma unroll
    for (int mf = 0; mf < 2; mf++) {
#pragma unroll
        for (int nf = 0; nf < 8; nf++) {
            int row = m0 + wm + mf * 16 + g;
            int col = e0 + wn + nf * 8 + 2 * t;
            int b = row >> 10, n = row & 1023;
            float4 c = acc[mf][nf];
            if (col < DIM_) {
                int h = col >> 6, d = col & 63;
                size_t base = (((size_t)b * H_ + h) * N_ + n) * D_ + d;
                *(float2*)&g_q[base] = make_float2(c.x, c.y);
                *(float2*)&g_q[base + 8 * D_] = make_float2(c.z, c.w);
            } else {
                int e2 = col - DIM_;
                int h = e2 >> 6, d = e2 & 63;
                size_t base = (((size_t)b * H_ + h) * D_ + d) * N_ + n;
                g_vT[base] = c.x;
                g_vT[base + N_] = c.y;
                g_vT[base + 8] = c.z;
                g_vT[base + N_ + 8] = c.w;
            }
        }
    }
}

// ============================================================================
// K2: stats — recompute scores tf32, accumulate sum & sumsq (no store)
// grid (8 n-tiles, 96 bh); q-tile 128, key-tile 64
// 8 warps = 4 n-groups (32 rows) x 2 m-halves (32 cols); warp tile 32x32
// dyn smem: Qs[128][68] + Ks[64][68] = 52224 B
// ============================================================================
__global__ __launch_bounds__(256) void stats_kernel(const float* __restrict__ Kx,
                                                    const float* __restrict__ Bias) {
    extern __shared__ uint32_t dynS[];
    uint32_t (*Qs)[68] = (uint32_t (*)[68])dynS;                 // 128 x 68
    uint32_t (*Ks)[68] = (uint32_t (*)[68])(dynS + 128 * 68);    // 64 x 68
    const int tid = threadIdx.x, lane = tid & 31, w = tid >> 5;
    const int g = lane >> 2, t = lane & 3;
    const int wn = (w >> 1) * 32, wm = (w & 1) * 32;
    const int bh = blockIdx.y, h = bh % H_;
    const int n0 = blockIdx.x * 128;

    const float* qp = g_q + ((size_t)bh * N_ + n0) * D_;
#pragma unroll
    for (int i = 0; i < 8; i++) {
        int f = tid + i * 256;          // [0,2048)
        int r = f >> 4;                 // 0..127
        int c4 = (f & 15) * 4;
        int bc = c4 & ~7, p2 = (c4 >> 2) & 1;
        float4 a = *(const float4*)&qp[(size_t)r * D_ + c4];
        Qs[r][bc + p2 + 0] = f2tf(a.x);
        Qs[r][bc + p2 + 2] = f2tf(a.y);
        Qs[r][bc + p2 + 4] = f2tf(a.z);
        Qs[r][bc + p2 + 6] = f2tf(a.w);
    }

    float s1 = 0.f, s2 = 0.f;
    for (int m0 = 0; m0 < N_; m0 += 64) {
        __syncthreads();
        const float* kp = Kx + ((size_t)h * N_ + m0) * D_;
#pragma unroll
        for (int i = 0; i < 4; i++) {
            int f = tid + i * 256;
            int r = f >> 4;
            int c4 = (f & 15) * 4;
            int bc = c4 & ~7, p2 = (c4 >> 2) & 1;
            float4 a = *(const float4*)&kp[(size_t)r * D_ + c4];
            Ks[r][bc + p2 + 0] = f2tf(a.x);
            Ks[r][bc + p2 + 2] = f2tf(a.y);
            Ks[r][bc + p2 + 4] = f2tf(a.z);
            Ks[r][bc + p2 + 6] = f2tf(a.w);
        }
        __syncthreads();

        float4 acc[2][4];
#pragma unroll
        for (int i = 0; i < 2; i++)
#pragma unroll
            for (int j = 0; j < 4; j++) acc[i][j] = make_float4(0.f, 0.f, 0.f, 0.f);

#pragma unroll
        for (int kb = 0; kb < 64; kb += 8) {
            uint2 A0[2], A1[2];
#pragma unroll
            for (int mf = 0; mf < 2; mf++) {
                A0[mf] = *(const uint2*)&Qs[wn + mf * 16 + g][kb + 2 * t];
                A1[mf] = *(const uint2*)&Qs[wn + mf * 16 + 8 + g][kb + 2 * t];
            }
            uint2 Bv[4];
#pragma unroll
            for (int nf = 0; nf < 4; nf++)
                Bv[nf] = *(const uint2*)&Ks[wm + nf * 8 + g][kb + 2 * t];
#pragma unroll
            for (int mf = 0; mf < 2; mf++)
#pragma unroll
                for (int nf = 0; nf < 4; nf++)
                    mma_tf32(acc[mf][nf], A0[mf].x, A1[mf].x, A0[mf].y, A1[mf].y,
                             Bv[nf].x, Bv[nf].y);
        }

#pragma unroll
        for (int mf = 0; mf < 2; mf++) {
#pragma unroll
            for (int nf = 0; nf < 4; nf++) {
                int rr = n0 + wn + mf * 16 + g;
                int cc = m0 + wm + nf * 8 + 2 * t;
                const float* bp = Bias + ((size_t)h * N_ + rr) * N_ + cc;
                float2 b0 = *(const float2*)bp;
                float2 b1 = *(const float2*)(bp + 8 * N_);
                float4 a = acc[mf][nf];
                float v0 = (a.x + b0.x) * SCALE_;
                float v1 = (a.y + b0.y) * SCALE_;
                float v2 = (a.z + b1.x) * SCALE_;
                float v3 = (a.w + b1.y) * SCALE_;
                s1 += v0 + v1 + v2 + v3;
                s2 += v0 * v0 + v1 * v1 + v2 * v2 + v3 * v3;
            }
        }
    }

    s1 = warp_red(s1);
    s2 = warp_red(s2);
    __shared__ float rs[2][8];
    if (lane == 0) { rs[0][w] = s1; rs[1][w] = s2; }
    __syncthreads();
    if (tid == 0) {
        float a = 0.f, b = 0.f;
#pragma unroll
        for (int i = 0; i < 8; i++) { a += rs[0][i]; b += rs[1][i]; }
        int bl = blockIdx.y * 8 + blockIdx.x;
        g_part[0][bl] = a;
        g_part[1][bl] = b;
    }
}

// ============================================================================
// K3: finalize g_h = gamma_h * rsqrt(var_h + eps). grid (12), 128 threads.
// partials: 8 blocks per (b,h); 64 entries per head
// ============================================================================
__global__ __launch_bounds__(128) void finalize_kernel(const float* __restrict__ gamma) {
    const int h = blockIdx.x, tid = threadIdx.x;
    float s1 = 0.f, s2 = 0.f;
    if (tid < 64) {
        int b = tid >> 3, tile = tid & 7;
        int idx = (b * H_ + h) * 8 + tile;
        s1 = g_part[0][idx];
        s2 = g_part[1][idx];
    }
    s1 = warp_red(s1);
    s2 = warp_red(s2);
    __shared__ float r1[4], r2[4];
    if ((tid & 31) == 0) { r1[tid >> 5] = s1; r2[tid >> 5] = s2; }
    __syncthreads();
    if (tid == 0) {
        float S1 = r1[0] + r1[1];
        float S2 = r2[0] + r2[1];
        const float cnt = (float)B_ * (float)N_ * (float)N_;
        float mean = S1 / cnt;
        float var = S2 / cnt - mean * mean;
        g_g[h] = gamma[h] * rsqrtf(var + EPS_);
    }
}

// ============================================================================
// K4: fused scores->exp->PV (flash style, tf32 mma both GEMMs)
// grid (16 n-tiles, 96 bh); q-tile 64, key-tile 64
// 8 warps = 4 n-groups (16 rows) x 2 halves (32 m / 32 d cols)
// dyn smem: Qs/Ks/Vs/Ps each [64][68] = 69632 B; static ls
// ============================================================================
__global__ __launch_bounds__(256) void fused_attn(const float* __restrict__ Kx,
                                                  const float* __restrict__ Bias) {
    extern __shared__ uint32_t dynF[];
    uint32_t (*Qs)[68] = (uint32_t (*)[68])dynF;
    uint32_t (*Ks)[68] = (uint32_t (*)[68])(dynF + 64 * 68);
    uint32_t (*Vs)[68] = (uint32_t (*)[68])(dynF + 2 * 64 * 68);
    uint32_t (*Ps)[68] = (uint32_t (*)[68])(dynF + 3 * 64 * 68);
    __shared__ float ls[2][64];

    const int tid = threadIdx.x, lane = tid & 31, w = tid >> 5;
    const int g = lane >> 2, t = lane & 3;
    const int wn = (w >> 1) * 16;     // 4 n-groups of 16 rows
    const int half = w & 1;
    const int wm = half * 32;         // S: m-half, PV: d-half
    const int bh = blockIdx.y, b = bh / H_, h = bh % H_;
    const int n0 = blockIdx.x * 64;
    const float sg = SCALE_ * g_g[h];
    const int pc0 = perm8(2 * t), pc1 = perm8(2 * t + 1);

    const float* qp = g_q + ((size_t)bh * N_ + n0) * D_;
#pragma unroll
    for (int i = 0; i < 4; i++) {
        int f = tid + i * 256;
        int r = f >> 4;
        int c4 = (f & 15) * 4;
        int bc = c4 & ~7, p2 = (c4 >> 2) & 1;
        float4 a = *(const float4*)&qp[(size_t)r * D_ + c4];
        Qs[r][bc + p2 + 0] = f2tf(a.x);
        Qs[r][bc + p2 + 2] = f2tf(a.y);
        Qs[r][bc + p2 + 4] = f2tf(a.z);
        Qs[r][bc + p2 + 6] = f2tf(a.w);
    }

    float4 O[4];
#pragma unroll
    for (int j = 0; j < 4; j++) O[j] = make_float4(0.f, 0.f, 0.f, 0.f);
    float l0 = 0.f, l1 = 0.f;

    for (int m0 = 0; m0 < N_; m0 += 64) {
        __syncthreads();   // prior PV done reading Vs/Ps (and 1st iter: Qs visible after next sync)
        // K tile: 64 m-rows x 64 d cols
        const float* kp = Kx + ((size_t)h * N_ + m0) * D_;
        const float* vp = g_vT + (size_t)bh * D_ * N_ + m0;
#pragma unroll
        for (int i = 0; i < 4; i++) {
            int f = tid + i * 256;          // [0,1024)
            int r = f >> 4;                 // 0..63
            int c4 = (f & 15) * 4;
            int bc = c4 & ~7, p2 = (c4 >> 2) & 1;
            float4 a = *(const float4*)&kp[(size_t)r * D_ + c4];
            Ks[r][bc + p2 + 0] = f2tf(a.x);
            Ks[r][bc + p2 + 2] = f2tf(a.y);
            Ks[r][bc + p2 + 4] = f2tf(a.z);
            Ks[r][bc + p2 + 6] = f2tf(a.w);
            // V^T tile: 64 d-rows x 64 m cols
            float4 v = *(const float4*)&vp[(size_t)r * N_ + c4];
            Vs[r][bc + p2 + 0] = f2tf(v.x);
            Vs[r][bc + p2 + 2] = f2tf(v.y);
            Vs[r][bc + p2 + 4] = f2tf(v.z);
            Vs[r][bc + p2 + 6] = f2tf(v.w);
        }
        __syncthreads();

        // S = Q @ K^T : warp computes 16n x 32m (4 nf)
        float4 S[4];
#pragma unroll
        for (int j = 0; j < 4; j++) S[j] = make_float4(0.f, 0.f, 0.f, 0.f);
#pragma unroll
        for (int kb = 0; kb < 64; kb += 8) {
            uint2 A0 = *(const uint2*)&Qs[wn + g][kb + 2 * t];
            uint2 A1 = *(const uint2*)&Qs[wn + 8 + g][kb + 2 * t];
#pragma unroll
            for (int nf = 0; nf < 4; nf++) {
                uint2 Bv = *(const uint2*)&Ks[wm + nf * 8 + g][kb + 2 * t];
                mma_tf32(S[nf], A0.x, A1.x, A0.y, A1.y, Bv.x, Bv.y);
            }
        }

        // epilogue: bias, exp, row-sum, write P (tf32, k-permuted along m)
#pragma unroll
        for (int nf = 0; nf < 4; nf++) {
            int rr = n0 + wn + g;
            int cc = m0 + wm + nf * 8 + 2 * t;
            const float* bp = Bias + ((size_t)h * N_ + rr) * N_ + cc;
            float2 b0 = *(const float2*)bp;
            float2 b1 = *(const float2*)(bp + 8 * N_);
            float p0 = __expf((S[nf].x + b0.x) * sg);
            float p1 = __expf((S[nf].y + b0.y) * sg);
            float p2v = __expf((S[nf].z + b1.x) * sg);
            float p3 = __expf((S[nf].w + b1.y) * sg);
            l0 += p0 + p1;
            l1 += p2v + p3;
            int base = wm + nf * 8;
            Ps[wn + g][base + pc0] = f2tf(p0);
            Ps[wn + g][base + pc1] = f2tf(p1);
            Ps[wn + 8 + g][base + pc0] = f2tf(p2v);
            Ps[wn + 8 + g][base + pc1] = f2tf(p3);
        }
        __syncthreads();   // P complete before PV

        // O += P @ V : warp covers rows [wn,wn+16), d cols [wm, wm+32)
#pragma unroll
        for (int kb = 0; kb < 64; kb += 8) {
            uint2 A0 = *(const uint2*)&Ps[wn + g][kb + 2 * t];
            uint2 A1 = *(const uint2*)&Ps[wn + 8 + g][kb + 2 * t];
#pragma unroll
            for (int df = 0; df < 4; df++) {
                uint2 Bv = *(const uint2*)&Vs[wm + df * 8 + g][kb + 2 * t];
                mma_tf32(O[df], A0.x, A1.x, A0.y, A1.y, Bv.x, Bv.y);
            }
        }
    }

    __syncthreads();
    // row sums: reduce over 4 lanes of each quad, then over the 2 m-halves
    l0 += __shfl_xor_sync(0xffffffffu, l0, 1);
    l0 += __shfl_xor_sync(0xffffffffu, l0, 2);
    l1 += __shfl_xor_sync(0xffffffffu, l1, 1);
    l1 += __shfl_xor_sync(0xffffffffu, l1, 2);
    if (t == 0) {
        ls[half][wn + g] = l0;
        ls[half][wn + 8 + g] = l1;
    }
    __syncthreads();

#pragma unroll
    for (int df = 0; df < 4; df++) {
        int rr = wn + g;
        int d = wm + df * 8 + 2 * t;
        float inv0 = 1.0f / (ls[0][rr] + ls[1][rr]);
        float inv1 = 1.0f / (ls[0][rr + 8] + ls[1][rr + 8]);
        size_t o = ((size_t)b * N_ + n0 + rr) * DIM_ + h * D_ + d;
        *(float2*)&g_obuf[o] = make_float2(O[df].x * inv0, O[df].y * inv0);
        *(float2*)&g_obuf[o + 8 * DIM_] = make_float2(O[df].z * inv1, O[df].w * inv1);
    }
}

// ============================================================================
// K5: proj (tf32): out[m,e] = sum_c obuf[m,c] Wp[e,c] + bp[e]; E=768
// ============================================================================
__global__ __launch_bounds__(256) void proj_gemm(const float* __restrict__ Wp,
                                                 const float* __restrict__ bp,
                                                 float* __restrict__ Out) {
    __shared__ uint32_t As[128][36];
    __shared__ uint32_t Bs[128][36];
    const int tid = threadIdx.x, lane = tid & 31, w = tid >> 5;
    const int g = lane >> 2, t = lane & 3;
    const int wm = (w & 3) * 32, wn = (w >> 2) * 64;
    const int m0 = blockIdx.y * 128, e0 = blockIdx.x * 128;

    float4 acc[2][8];
#pragma unroll
    for (int i = 0; i < 2; i++)
#pragma unroll
        for (int j = 0; j < 8; j++) acc[i][j] = make_float4(0.f, 0.f, 0.f, 0.f);

    for (int kc = 0; kc < DIM_; kc += 32) {
#pragma unroll
        for (int i = 0; i < 4; i++) {
            int f = tid + i * 256;
            int r = f >> 3;
            int c4 = (f & 7) * 4;
            int bc = c4 & ~7, p2 = (c4 >> 2) & 1;
            float4 a = *(const float4*)&g_obuf[(size_t)(m0 + r) * DIM_ + kc + c4];
            As[r][bc + p2 + 0] = f2tf(a.x);
            As[r][bc + p2 + 2] = f2tf(a.y);
            As[r][bc + p2 + 4] = f2tf(a.z);
            As[r][bc + p2 + 6] = f2tf(a.w);
            float4 bv = *(const float4*)&Wp[(size_t)(e0 + r) * DIM_ + kc + c4];
            Bs[r][bc + p2 + 0] = f2tf(bv.x);
            Bs[r][bc + p2 + 2] = f2tf(bv.y);
            Bs[r][bc + p2 + 4] = f2tf(bv.z);
            Bs[r][bc + p2 + 6] = f2tf(bv.w);
        }
        __syncthreads();
#pragma unroll
        for (int ks = 0; ks < 4; ks++) {
            int kb = ks * 8;
            uint2 A0[2], A1[2];
#pragma unroll
            for (int mf = 0; mf < 2; mf++) {
                A0[mf] = *(const uint2*)&As[wm + mf * 16 + g][kb + 2 * t];
                A1[mf] = *(const uint2*)&As[wm + mf * 16 + 8 + g][kb + 2 * t];
            }
            uint2 Bv[8];
#pragma unroll
            for (int nf = 0; nf < 8; nf++)
                Bv[nf] = *(const uint2*)&Bs[wn + nf * 8 + g][kb + 2 * t];
#pragma unroll
            for (int mf = 0; mf < 2; mf++)
#pragma unroll
                for (int nf = 0; nf < 8; nf++)
                    mma_tf32(acc[mf][nf], A0[mf].x, A1[mf].x, A0[mf].y, A1[mf].y,
                             Bv[nf].x, Bv[nf].y);
        }
        __syncthreads();
    }

#pragma unroll
    for (int mf = 0; mf < 2; mf++) {
#pragma unroll
        for (int nf = 0; nf < 8; nf++) {
            int row = m0 + wm + mf * 16 + g;
            int col = e0 + wn + nf * 8 + 2 * t;
            float2 bb = *(const float2*)&bp[col];
            float4 c = acc[mf][nf];
            *(float2*)&Out[(size_t)row * DIM_ + col] =
                make_float2(c.x + bb.x, c.y + bb.y);
            *(float2*)&Out[(size_t)(row + 8) * DIM_ + col] =
                make_float2(c.z + bb.x, c.w + bb.y);
        }
    }
}

// ============================================================================
// launch
// ============================================================================
extern "C" void kernel_launch(void* const* d_in, const int* in_sizes, int n_in,
                              void* d_out, int out_size) {
    const float* x        = (const float*)d_in[0];
    const float* w_qv     = (const float*)d_in[1];
    const float* ext_k    = (const float*)d_in[2];
    const float* ext_bias = (const float*)d_in[3];
    const float* bn_gamma = (const float*)d_in[4];
    // d_in[5] = bn_beta: cancels inside softmax (constant along key axis)
    const float* w_proj   = (const float*)d_in[6];
    const float* b_proj   = (const float*)d_in[7];
    float* out = (float*)d_out;

    const int dynStats = (128 * 68 + 64 * 68) * 4;   // 52224 B
    const int dynFused = 4 * 64 * 68 * 4;            // 69632 B
    cudaFuncSetAttribute(stats_kernel, cudaFuncAttributeMaxDynamicSharedMemorySize, dynStats);
    cudaFuncSetAttribute(fused_attn, cudaFuncAttributeMaxDynamicSharedMemorySize, dynFused);

    qv_gemm<<<dim3(12, 64), 256>>>(x, w_qv);
    stats_kernel<<<dim3(8, 96), 256, dynStats>>>(ext_k, ext_bias);
    finalize_kernel<<<dim3(H_), 128>>>(bn_gamma);
    fused_attn<<<dim3(16, 96), 256, dynFused>>>(ext_k, ext_bias);
    proj_gemm<<<dim3(6, 64), 256>>>(w_proj, b_proj, out);
}